// round 13
// baseline (speedup 1.0000x reference)
#include <cuda_runtime.h>
#include <cuda_fp16.h>
#include <cstdint>

// Problem constants
#define B_  4
#define L_  2048
#define D_  512
#define H_  8
#define DK_ 64
#define M_  (B_ * L_)
#define LOG2E 1.44269504f

// fp16 copies of inputs/weights (prep kernel), mask premultiplied by log2e (fp16).
__device__ __half g_xq16[M_ * D_];
__device__ __half g_xk16[M_ * D_];
__device__ __half g_xv16[M_ * D_];
__device__ __half g_wq16[D_ * D_];
__device__ __half g_wk16[D_ * D_];
__device__ __half g_wv16[D_ * D_];
__device__ __half g_wo16[D_ * D_];
__device__ __half g_mlh[L_ * L_];

// Projections (fp16; Q pre-scaled by 0.125*log2e), attention output (fp16)
// in the reference's flattening order [H, Lq, B, Dv].
__device__ __half g_qh[B_ * L_ * H_ * DK_];
__device__ __half g_kh[B_ * L_ * H_ * DK_];
__device__ __half g_vh[B_ * L_ * H_ * DK_];
__device__ __half g_xth[B_ * L_ * H_ * DK_];

// ---------------------------------------------------------------------------
// helpers
// ---------------------------------------------------------------------------
__device__ __forceinline__ void mma_f16(float c[4], const uint32_t a[4],
                                        uint32_t b0, uint32_t b1) {
    asm("mma.sync.aligned.m16n8k16.row.col.f32.f16.f16.f32 "
        "{%0,%1,%2,%3}, {%4,%5,%6,%7}, {%8,%9}, {%0,%1,%2,%3};\n"
        : "+f"(c[0]), "+f"(c[1]), "+f"(c[2]), "+f"(c[3])
        : "r"(a[0]), "r"(a[1]), "r"(a[2]), "r"(a[3]), "r"(b0), "r"(b1));
}

__device__ __forceinline__ uint32_t pack_h2(float lo, float hi) {
    uint32_t u;
    asm("cvt.rn.f16x2.f32 %0, %1, %2;" : "=r"(u) : "f"(hi), "f"(lo));
    return u;
}

__device__ __forceinline__ float ex2f(float x) {
    float r;
    asm("ex2.approx.f32 %0, %1;" : "=f"(r) : "f"(x));
    return r;
}

__device__ __forceinline__ uint32_t smem_u32(const void* p) {
    uint32_t a;
    asm("{ .reg .u64 t; cvta.to.shared.u64 t, %1; cvt.u32.u64 %0, t; }"
        : "=r"(a) : "l"(p));
    return a;
}

#define LDSM_X4(r0, r1, r2, r3, addr) \
    asm volatile("ldmatrix.sync.aligned.m8n8.x4.shared.b16 {%0,%1,%2,%3}, [%4];" \
                 : "=r"(r0), "=r"(r1), "=r"(r2), "=r"(r3) : "r"(addr))

#define LDSM_X4_T(r0, r1, r2, r3, addr) \
    asm volatile("ldmatrix.sync.aligned.m8n8.x4.trans.shared.b16 {%0,%1,%2,%3}, [%4];" \
                 : "=r"(r0), "=r"(r1), "=r"(r2), "=r"(r3) : "r"(addr))

#define CP_ASYNC16(dst, src) \
    asm volatile("cp.async.cg.shared.global [%0], [%1], 16;" :: "r"(dst), "l"(src))

extern __shared__ __half dynsm[];

// ---------------------------------------------------------------------------
// Prep: fp32->fp16 conversions + mask*log2e (fp16). seg = blockIdx.y.
// ---------------------------------------------------------------------------
__global__ void prep_f16(const float* __restrict__ q, const float* __restrict__ k,
                         const float* __restrict__ v, const float* __restrict__ wq,
                         const float* __restrict__ wk, const float* __restrict__ wv,
                         const float* __restrict__ wo, const float* __restrict__ mask)
{
    const int seg = blockIdx.y;
    const float* src = nullptr;
    __half* dst = nullptr;
    int n4 = 0;
    float sc = 1.0f;
    switch (seg) {
        case 0: src = q;    dst = g_xq16; n4 = M_ * D_ / 4; break;
        case 1: src = k;    dst = g_xk16; n4 = M_ * D_ / 4; break;
        case 2: src = v;    dst = g_xv16; n4 = M_ * D_ / 4; break;
        case 3: src = wq;   dst = g_wq16; n4 = D_ * D_ / 4; break;
        case 4: src = wk;   dst = g_wk16; n4 = D_ * D_ / 4; break;
        case 5: src = wv;   dst = g_wv16; n4 = D_ * D_ / 4; break;
        case 6: src = wo;   dst = g_wo16; n4 = D_ * D_ / 4; break;
        case 7: src = mask; dst = g_mlh;  n4 = L_ * L_ / 4; sc = LOG2E; break;
    }
    const int stride = gridDim.x * blockDim.x;
    const float4* s4 = reinterpret_cast<const float4*>(src);
    uint2* d2 = reinterpret_cast<uint2*>(dst);
    for (int i = blockIdx.x * blockDim.x + threadIdx.x; i < n4; i += stride) {
        float4 a = s4[i];
        uint2 u = {pack_h2(a.x * sc, a.y * sc), pack_h2(a.z * sc, a.w * sc)};
        d2[i] = u;
    }
}

// ---------------------------------------------------------------------------
// QKV GEMM 64x128 CTA tile, 128 threads (4 warps of m64n32), BK=32,
// 3-stage cp.async ring, one barrier per k-step, fp16 mma, fp32 accumulate.
// ---------------------------------------------------------------------------
#define GAP 40    // A pitch (halves)
#define GBP 136   // B pitch (halves, 128-wide tile)
#define GA_TILE (64 * GAP)    // 2560 halves
#define GB_TILE (32 * GBP)    // 4352 halves
#define GEMM_SMEM ((3 * GA_TILE + 3 * GB_TILE) * 2)   // 41472 B

__device__ __forceinline__ void gemm_stage(uint32_t adst, uint32_t bdst,
                                           const __half* __restrict__ A,
                                           const __half* __restrict__ W,
                                           int m0, int n0, int kb)
{
    const int tid = threadIdx.x;
#pragma unroll
    for (int i = 0; i < 2; i++) {
        int f   = tid + (i << 7);
        int row = f >> 2;
        int c8  = (f & 3) << 3;
        CP_ASYNC16(adst + (uint32_t)(row * GAP + c8) * 2u,
                   A + (size_t)(m0 + row) * D_ + kb + c8);
    }
#pragma unroll
    for (int i = 0; i < 4; i++) {
        int f   = tid + (i << 7);
        int row = f >> 4;
        int c8  = (f & 15) << 3;
        CP_ASYNC16(bdst + (uint32_t)(row * GBP + c8) * 2u,
                   W + (size_t)(kb + row) * D_ + n0 + c8);
    }
    asm volatile("cp.async.commit_group;");
}

__global__ __launch_bounds__(128)
void gemm_qkv(const float* __restrict__ bq, const float* __restrict__ bk,
              const float* __restrict__ bv)
{
    const int z = blockIdx.z;
    const __half* A = (z == 0) ? g_xq16 : (z == 1) ? g_xk16 : g_xv16;
    const __half* W = (z == 0) ? g_wq16 : (z == 1) ? g_wk16 : g_wv16;
    const float* bias = (z == 0) ? bq : (z == 1) ? bk : bv;
    __half* C = (z == 0) ? g_qh : (z == 1) ? g_kh : g_vh;
    const float osc = (z == 0) ? 0.125f * LOG2E : 1.0f;

    const uint32_t abase = smem_u32(dynsm);
    const uint32_t bbase = abase + 3u * GA_TILE * 2u;

    const int tid  = threadIdx.x;
    const int wc   = tid >> 5;
    const int lane = tid & 31;
    const int g    = lane >> 2;
    const int c    = lane & 3;
    const int m0   = blockIdx.x << 6;
    const int n0   = blockIdx.y << 7;

    const int lr8  = lane & 7;
    const int lhi  = (lane >> 3) & 1;
    const int lcol = lane >> 4;

    gemm_stage(abase, bbase, A, W, m0, n0, 0);
    gemm_stage(abase + GA_TILE * 2u, bbase + GB_TILE * 2u, A, W, m0, n0, 32);

    float acc[4][4][4];
#pragma unroll
    for (int mt = 0; mt < 4; mt++)
#pragma unroll
        for (int nt = 0; nt < 4; nt++)
#pragma unroll
            for (int r = 0; r < 4; r++) acc[mt][nt][r] = 0.f;

    const int niter = D_ / 32;
    for (int it = 0; it < niter; it++) {
        asm volatile("cp.async.wait_group 1;" ::: "memory");
        __syncthreads();

        const uint32_t as = abase + (uint32_t)(it % 3) * GA_TILE * 2u;
        const uint32_t bs = bbase + (uint32_t)(it % 3) * GB_TILE * 2u;

#pragma unroll
        for (int ks = 0; ks < 2; ks++) {
            uint32_t a[4][4];
#pragma unroll
            for (int mt = 0; mt < 4; mt++) {
                uint32_t addr = as + (uint32_t)(
                    (mt * 16 + lr8 + lhi * 8) * GAP + ks * 16 + lcol * 8) * 2u;
                LDSM_X4(a[mt][0], a[mt][1], a[mt][2], a[mt][3], addr);
            }
            uint32_t bfr[2][4];
#pragma unroll
            for (int np = 0; np < 2; np++) {
                uint32_t addr = bs + (uint32_t)(
                    (ks * 16 + lr8 + lhi * 8) * GBP
                    + wc * 32 + np * 16 + lcol * 8) * 2u;
                LDSM_X4_T(bfr[np][0], bfr[np][1], bfr[np][2], bfr[np][3], addr);
            }
#pragma unroll
            for (int mt = 0; mt < 4; mt++)
#pragma unroll
                for (int nt = 0; nt < 4; nt++)
                    mma_f16(acc[mt][nt], a[mt],
                            bfr[nt >> 1][(nt & 1) * 2],
                            bfr[nt >> 1][(nt & 1) * 2 + 1]);
        }

        if (it + 2 < niter)
            gemm_stage(abase + (uint32_t)((it + 2) % 3) * GA_TILE * 2u,
                       bbase + (uint32_t)((it + 2) % 3) * GB_TILE * 2u,
                       A, W, m0, n0, (it + 2) * 32);
        else
            asm volatile("cp.async.commit_group;");
    }

#pragma unroll
    for (int nt = 0; nt < 4; nt++) {
        int col = n0 + wc * 32 + nt * 8 + 2 * c;
        float bx = bias[col], by = bias[col + 1];
#pragma unroll
        for (int mt = 0; mt < 4; mt++) {
            int row = m0 + mt * 16 + g;
            *reinterpret_cast<uint32_t*>(C + (size_t)row * D_ + col) =
                pack_h2((acc[mt][nt][0] + bx) * osc, (acc[mt][nt][1] + by) * osc);
            *reinterpret_cast<uint32_t*>(C + (size_t)(row + 8) * D_ + col) =
                pack_h2((acc[mt][nt][2] + bx) * osc, (acc[mt][nt][3] + by) * osc);
        }
    }
}

// ---------------------------------------------------------------------------
// O-projection GEMM: 64x64 CTA tile (4 warps of m64n16), BK=64 (8 iterations
// of 32 mma each -> barrier overhead halved vs BK=32). 3-stage ring.
// fp32 output + bias. Grid 1024 CTAs.
// ---------------------------------------------------------------------------
#define GAP2 72                    // A and B pitch (halves, 64-wide)
#define GO_TILE (64 * GAP2)        // 4608 halves = 9216 B per tile
#define GEMM2_SMEM (6 * GO_TILE * 2)   // 3 stages x (A+B) = 55296 B

__device__ __forceinline__ void gemm2_stage(uint32_t adst, uint32_t bdst,
                                            int m0, int n0, int kb)
{
    const int tid = threadIdx.x;
#pragma unroll
    for (int i = 0; i < 4; i++) {
        int f   = tid + (i << 7);
        int row = f >> 3;             // 0..63
        int c8  = (f & 7) << 3;       // 0..56
        CP_ASYNC16(adst + (uint32_t)(row * GAP2 + c8) * 2u,
                   g_xth + (size_t)(m0 + row) * D_ + kb + c8);
        CP_ASYNC16(bdst + (uint32_t)(row * GAP2 + c8) * 2u,
                   g_wo16 + (size_t)(kb + row) * D_ + n0 + c8);
    }
    asm volatile("cp.async.commit_group;");
}

__global__ __launch_bounds__(128)
void gemm_o(const float* __restrict__ bo, float* __restrict__ out)
{
    const uint32_t abase = smem_u32(dynsm);
    const uint32_t bbase = abase + 3u * GO_TILE * 2u;

    const int tid  = threadIdx.x;
    const int wc   = tid >> 5;
    const int lane = tid & 31;
    const int g    = lane >> 2;
    const int c    = lane & 3;
    const int m0   = blockIdx.x << 6;
    const int n0   = blockIdx.y << 6;

    const int lr8  = lane & 7;
    const int lhi  = (lane >> 3) & 1;
    const int lcol = lane >> 4;

    gemm2_stage(abase, bbase, m0, n0, 0);
    gemm2_stage(abase + GO_TILE * 2u, bbase + GO_TILE * 2u, m0, n0, 64);

    float acc[4][2][4];
#pragma unroll
    for (int mt = 0; mt < 4; mt++)
#pragma unroll
        for (int nt = 0; nt < 2; nt++)
#pragma unroll
            for (int r = 0; r < 4; r++) acc[mt][nt][r] = 0.f;

    const int niter = D_ / 64;   // 8
    for (int it = 0; it < niter; it++) {
        asm volatile("cp.async.wait_group 1;" ::: "memory");
        __syncthreads();

        const uint32_t as = abase + (uint32_t)(it % 3) * GO_TILE * 2u;
        const uint32_t bs = bbase + (uint32_t)(it % 3) * GO_TILE * 2u;

#pragma unroll
        for (int ks = 0; ks < 4; ks++) {
            uint32_t a[4][4];
#pragma unroll
            for (int mt = 0; mt < 4; mt++) {
                uint32_t addr = as + (uint32_t)(
                    (mt * 16 + lr8 + lhi * 8) * GAP2 + ks * 16 + lcol * 8) * 2u;
                LDSM_X4(a[mt][0], a[mt][1], a[mt][2], a[mt][3], addr);
            }
            uint32_t b0, b1, b2, b3;
            {
                uint32_t addr = bs + (uint32_t)(
                    (ks * 16 + lr8 + lhi * 8) * GAP2 + wc * 16 + lcol * 8) * 2u;
                LDSM_X4_T(b0, b1, b2, b3, addr);
            }
#pragma unroll
            for (int mt = 0; mt < 4; mt++) {
                mma_f16(acc[mt][0], a[mt], b0, b1);
                mma_f16(acc[mt][1], a[mt], b2, b3);
            }
        }

        if (it + 2 < niter)
            gemm2_stage(abase + (uint32_t)((it + 2) % 3) * GO_TILE * 2u,
                        bbase + (uint32_t)((it + 2) % 3) * GO_TILE * 2u,
                        m0, n0, (it + 2) * 64);
        else
            asm volatile("cp.async.commit_group;");
    }

#pragma unroll
    for (int nt = 0; nt < 2; nt++) {
        int col = n0 + wc * 16 + nt * 8 + 2 * c;
        float bx = bo[col], by = bo[col + 1];
#pragma unroll
        for (int mt = 0; mt < 4; mt++) {
            int row = m0 + mt * 16 + g;
            *reinterpret_cast<float2*>(out + (size_t)row * D_ + col) =
                make_float2(acc[mt][nt][0] + bx, acc[mt][nt][1] + by);
            *reinterpret_cast<float2*>(out + (size_t)(row + 8) * D_ + col) =
                make_float2(acc[mt][nt][2] + bx, acc[mt][nt][3] + by);
        }
    }
}

// ---------------------------------------------------------------------------
// Flash attention: m16 warps, 3-stage ring, one barrier per tile.
// Mask stored fp16 (bandwidth) but softmax math in fp32 (precision):
// h2->f2 convert, fp32 add, ex2.approx.f32, pack to fp16 P frags.
// Row sum via ones-matrix mma.
// ---------------------------------------------------------------------------
#define FPH 72                 // K/V smem pitch (halves)
#define FTILE_H (64 * FPH)     // 9216 B
#define FLASH_SMEM (6 * FTILE_H * 2)   // 55296 B
#define ONES_H2 0x3C003C00u

__device__ __forceinline__ void stage_kv(uint32_t kdst, uint32_t vdst,
                                         int b, int h, int k0)
{
    const int tid = threadIdx.x;
#pragma unroll
    for (int i = 0; i < 4; i++) {
        int f   = tid + (i << 7);
        int row = f >> 3;
        int s8  = (f & 7) << 3;
        size_t gidx = (((size_t)b * L_ + k0 + row) * H_ + h) * DK_ + s8;
        uint32_t off = (uint32_t)(row * FPH + s8) * 2u;
        CP_ASYNC16(kdst + off, g_kh + gidx);
        CP_ASYNC16(vdst + off, g_vh + gidx);
    }
    asm volatile("cp.async.commit_group;");
}

__global__ __launch_bounds__(128)
void flash_f16()
{
    const uint32_t base = smem_u32(dynsm);

    const int tid  = threadIdx.x;
    const int warp = tid >> 5;
    const int lane = tid & 31;
    const int g    = lane >> 2;
    const int c    = lane & 3;
    const int q0   = blockIdx.x << 6;
    const int h    = blockIdx.y;
    const int b    = blockIdx.z;
    const int qrow = q0 + warp * 16;

    uint32_t ks[3], vs[3];
#pragma unroll
    for (int i = 0; i < 3; i++) {
        ks[i] = base + (uint32_t)(i * FTILE_H) * 2u;
        vs[i] = base + (uint32_t)((3 + i) * FTILE_H) * 2u;
    }

    const int lr8 = lane & 7;
    const int lhi = (lane >> 3) & 1;
    const int lcol = lane >> 4;
    const uint32_t k_lane_off =
        (uint32_t)(lr8 * FPH + (lane >> 3) * 8) * 2u;
    const uint32_t v_lane_off =
        (uint32_t)((lr8 + lhi * 8) * FPH + lcol * 8) * 2u;

    stage_kv(ks[0], vs[0], b, h, 0);
    stage_kv(ks[1], vs[1], b, h, 64);

    // Q fragments (fp16, pre-scaled by 0.125*log2e)
    uint32_t qf[4][4];
    {
        const __half* qp = g_qh + (((size_t)b * L_ + qrow) * H_ + h) * DK_;
#pragma unroll
        for (int kb = 0; kb < 4; kb++) {
            int d0 = kb * 16 + 2 * c;
            qf[kb][0] = *reinterpret_cast<const uint32_t*>(
                qp + (size_t)(g)     * (H_ * DK_) + d0);
            qf[kb][1] = *reinterpret_cast<const uint32_t*>(
                qp + (size_t)(g + 8) * (H_ * DK_) + d0);
            qf[kb][2] = *reinterpret_cast<const uint32_t*>(
                qp + (size_t)(g)     * (H_ * DK_) + d0 + 8);
            qf[kb][3] = *reinterpret_cast<const uint32_t*>(
                qp + (size_t)(g + 8) * (H_ * DK_) + d0 + 8);
        }
    }

    float o[8][4];
    float lsum[4] = {0.f, 0.f, 0.f, 0.f};
#pragma unroll
    for (int nt = 0; nt < 8; nt++)
#pragma unroll
        for (int r = 0; r < 4; r++) o[nt][r] = 0.f;

    const __half* mbase0 = g_mlh + (size_t)(qrow + g) * L_;
    const __half* mbase1 = mbase0 + 8 * L_;

    for (int t = 0; t < 32; t++) {
        asm volatile("cp.async.wait_group 1;" ::: "memory");
        __syncthreads();

        const uint32_t kb_sm = ks[t % 3];
        const uint32_t vb_sm = vs[t % 3];
        const int k0 = t << 6;

        // Prefetch fp16 mask tile before QK mma (latency overlaps tensor work)
        uint32_t mh0[8], mh1[8];
#pragma unroll
        for (int nt = 0; nt < 8; nt++) {
            int col = k0 + nt * 8 + 2 * c;
            mh0[nt] = *reinterpret_cast<const uint32_t*>(mbase0 + col);
            mh1[nt] = *reinterpret_cast<const uint32_t*>(mbase1 + col);
        }

        // S' = (Q*log2e/8) K^T
        float s[8][4];
#pragma unroll
        for (int nt = 0; nt < 8; nt++)
#pragma unroll
            for (int r = 0; r < 4; r++) s[nt][r] = 0.f;

#pragma unroll
        for (int nt = 0; nt < 8; nt++) {
#pragma unroll
            for (int kb2 = 0; kb2 < 2; kb2++) {
                uint32_t r0, r1, r2, r3;
                uint32_t addr = kb_sm
                    + (uint32_t)(nt * 8 * FPH + kb2 * 32) * 2u + k_lane_off;
                LDSM_X4(r0, r1, r2, r3, addr);
                mma_f16(s[nt], qf[2 * kb2],     r0, r1);
                mma_f16(s[nt], qf[2 * kb2 + 1], r2, r3);
            }
        }

        // fp32 softmax: convert fp16 mask up, add, ex2.f32, pack P
        uint32_t ph[8][2];
#pragma unroll
        for (int nt = 0; nt < 8; nt++) {
            float2 m0f = __half22float2(
                *reinterpret_cast<const __half2*>(&mh0[nt]));
            float2 m1f = __half22float2(
                *reinterpret_cast<const __half2*>(&mh1[nt]));
            float p0 = ex2f(s[nt][0] + m0f.x);
            float p1 = ex2f(s[nt][1] + m0f.y);
            float p2 = ex2f(s[nt][2] + m1f.x);
            float p3 = ex2f(s[nt][3] + m1f.y);
            ph[nt][0] = pack_h2(p0, p1);
            ph[nt][1] = pack_h2(p2, p3);
        }

        // O += P V ; l += P @ ones
#pragma unroll
        for (int j = 0; j < 4; j++) {
            uint32_t a[4] = {ph[2 * j][0], ph[2 * j][1],
                             ph[2 * j + 1][0], ph[2 * j + 1][1]};
            mma_f16(lsum, a, ONES_H2, ONES_H2);
#pragma unroll
            for (int np = 0; np < 4; np++) {
                uint32_t r0, r1, r2, r3;
                uint32_t addr = vb_sm
                    + (uint32_t)(j * 16 * FPH + np * 16) * 2u + v_lane_off;
                LDSM_X4_T(r0, r1, r2, r3, addr);
                mma_f16(o[2 * np],     a, r0, r1);
                mma_f16(o[2 * np + 1], a, r2, r3);
            }
        }

        if (t + 2 < 32)
            stage_kv(ks[(t + 2) % 3], vs[(t + 2) % 3], b, h, (t + 2) << 6);
        else
            asm volatile("cp.async.commit_group;");
    }

    float inv0 = 1.0f / lsum[0], inv1 = 1.0f / lsum[2];

    // Epilogue: write g_xth (fp16) in [H, Lq, B, Dv] flat order
#pragma unroll
    for (int nt = 0; nt < 8; nt++) {
        int dv = nt * 8 + 2 * c;
        size_t base0 = (((size_t)h * L_ + qrow + g) * B_ + b) * DK_ + dv;
        size_t base1 = (((size_t)h * L_ + qrow + g + 8) * B_ + b) * DK_ + dv;
        *reinterpret_cast<uint32_t*>(g_xth + base0) =
            pack_h2(o[nt][0] * inv0, o[nt][1] * inv0);
        *reinterpret_cast<uint32_t*>(g_xth + base1) =
            pack_h2(o[nt][2] * inv1, o[nt][3] * inv1);
    }
}

// ---------------------------------------------------------------------------
extern "C" void kernel_launch(void* const* d_in, const int* in_sizes, int n_in,
                              void* d_out, int out_size)
{
    const float* query = (const float*)d_in[0];
    const float* key   = (const float*)d_in[1];
    const float* value = (const float*)d_in[2];
    const float* mask  = (const float*)d_in[3];
    const float* Wq    = (const float*)d_in[4];
    const float* bq    = (const float*)d_in[5];
    const float* Wk    = (const float*)d_in[6];
    const float* bk    = (const float*)d_in[7];
    const float* Wv    = (const float*)d_in[8];
    const float* bv    = (const float*)d_in[9];
    const float* Wo    = (const float*)d_in[10];
    const float* bo    = (const float*)d_in[11];
    float* out = (float*)d_out;

    cudaFuncSetAttribute(gemm_qkv,
                         cudaFuncAttributeMaxDynamicSharedMemorySize, GEMM_SMEM);
    cudaFuncSetAttribute(gemm_o,
                         cudaFuncAttributeMaxDynamicSharedMemorySize, GEMM2_SMEM);
    cudaFuncSetAttribute(flash_f16,
                         cudaFuncAttributeMaxDynamicSharedMemorySize, FLASH_SMEM);

    prep_f16<<<dim3(512, 8), 256>>>(query, key, value, Wq, Wk, Wv, Wo, mask);

    gemm_qkv<<<dim3(M_ / 64, D_ / 128, 3), 128, GEMM_SMEM>>>(bq, bk, bv);

    flash_f16<<<dim3(L_ / 64, H_, B_), 128, FLASH_SMEM>>>();

    gemm_o<<<dim3(M_ / 64, D_ / 64), 128, GEMM2_SMEM>>>(bo, out);
}

// round 14
// speedup vs baseline: 1.1598x; 1.1598x over previous
#include <cuda_runtime.h>
#include <cuda_fp16.h>
#include <cstdint>

// Problem constants
#define B_  4
#define L_  2048
#define D_  512
#define H_  8
#define DK_ 64
#define M_  (B_ * L_)
#define LOG2E 1.44269504f

// fp16 copies of inputs/weights (prep kernel).
__device__ __half g_xq16[M_ * D_];
__device__ __half g_xk16[M_ * D_];
__device__ __half g_xv16[M_ * D_];
__device__ __half g_wq16[D_ * D_];
__device__ __half g_wk16[D_ * D_];
__device__ __half g_wv16[D_ * D_];
__device__ __half g_wo16[D_ * D_];

// Mask in FRAGMENT order (fp16 pairs, *log2e):
// g_mp[((qb*32 + t)*4 + w)*32 + lane][j], j = nt*2 + half.
// value j: half2( mask[q][kv], mask[q][kv+1] ), q = qb*64 + w*16 + g + half*8,
// kv = t*64 + nt*8 + 2c  (g = lane>>2, c = lane&3).
__device__ uint32_t g_mp[32 * 32 * 4 * 32 * 16];

// Projections (fp16; Q pre-scaled by 0.125*log2e), attention output (fp16)
// in the reference's flattening order [H, Lq, B, Dv].
__device__ __half g_qh[B_ * L_ * H_ * DK_];
__device__ __half g_kh[B_ * L_ * H_ * DK_];
__device__ __half g_vh[B_ * L_ * H_ * DK_];
__device__ __half g_xth[B_ * L_ * H_ * DK_];

// ---------------------------------------------------------------------------
// helpers
// ---------------------------------------------------------------------------
__device__ __forceinline__ void mma_f16(float c[4], const uint32_t a[4],
                                        uint32_t b0, uint32_t b1) {
    asm("mma.sync.aligned.m16n8k16.row.col.f32.f16.f16.f32 "
        "{%0,%1,%2,%3}, {%4,%5,%6,%7}, {%8,%9}, {%0,%1,%2,%3};\n"
        : "+f"(c[0]), "+f"(c[1]), "+f"(c[2]), "+f"(c[3])
        : "r"(a[0]), "r"(a[1]), "r"(a[2]), "r"(a[3]), "r"(b0), "r"(b1));
}

__device__ __forceinline__ uint32_t pack_h2(float lo, float hi) {
    uint32_t u;
    asm("cvt.rn.f16x2.f32 %0, %1, %2;" : "=r"(u) : "f"(hi), "f"(lo));
    return u;
}

__device__ __forceinline__ float ex2f(float x) {
    float r;
    asm("ex2.approx.f32 %0, %1;" : "=f"(r) : "f"(x));
    return r;
}

__device__ __forceinline__ uint32_t smem_u32(const void* p) {
    uint32_t a;
    asm("{ .reg .u64 t; cvta.to.shared.u64 t, %1; cvt.u32.u64 %0, t; }"
        : "=r"(a) : "l"(p));
    return a;
}

#define LDSM_X4(r0, r1, r2, r3, addr) \
    asm volatile("ldmatrix.sync.aligned.m8n8.x4.shared.b16 {%0,%1,%2,%3}, [%4];" \
                 : "=r"(r0), "=r"(r1), "=r"(r2), "=r"(r3) : "r"(addr))

#define LDSM_X4_T(r0, r1, r2, r3, addr) \
    asm volatile("ldmatrix.sync.aligned.m8n8.x4.trans.shared.b16 {%0,%1,%2,%3}, [%4];" \
                 : "=r"(r0), "=r"(r1), "=r"(r2), "=r"(r3) : "r"(addr))

#define CP_ASYNC16(dst, src) \
    asm volatile("cp.async.cg.shared.global [%0], [%1], 16;" :: "r"(dst), "l"(src))

extern __shared__ __half dynsm[];

// ---------------------------------------------------------------------------
// Prep: fp32->fp16 conversions; seg 7 permutes the mask into fragment order.
// ---------------------------------------------------------------------------
__global__ void prep_f16(const float* __restrict__ q, const float* __restrict__ k,
                         const float* __restrict__ v, const float* __restrict__ wq,
                         const float* __restrict__ wk, const float* __restrict__ wv,
                         const float* __restrict__ wo, const float* __restrict__ mask)
{
    const int seg = blockIdx.y;
    if (seg == 7) {
        // One thread per (qb, t, w, lane): writes 16 contiguous u32 (64B).
        int idx = blockIdx.x * blockDim.x + threadIdx.x;   // 0..131071
        int lane = idx & 31;
        int w    = (idx >> 5) & 3;
        int t    = (idx >> 7) & 31;
        int qb   = idx >> 12;                               // 0..31
        int g    = lane >> 2;
        int c    = lane & 3;
        uint32_t out[16];
#pragma unroll
        for (int j = 0; j < 16; j++) {
            int nt   = j >> 1;
            int half = j & 1;
            int qrow = qb * 64 + w * 16 + g + half * 8;
            int kv   = t * 64 + nt * 8 + 2 * c;
            float2 mv = *reinterpret_cast<const float2*>(
                mask + (size_t)qrow * L_ + kv);
            out[j] = pack_h2(mv.x * LOG2E, mv.y * LOG2E);
        }
        uint4* dst = reinterpret_cast<uint4*>(g_mp + (size_t)idx * 16);
        dst[0] = make_uint4(out[0], out[1], out[2], out[3]);
        dst[1] = make_uint4(out[4], out[5], out[6], out[7]);
        dst[2] = make_uint4(out[8], out[9], out[10], out[11]);
        dst[3] = make_uint4(out[12], out[13], out[14], out[15]);
        return;
    }

    const float* src = nullptr;
    __half* dst = nullptr;
    int n4 = 0;
    switch (seg) {
        case 0: src = q;  dst = g_xq16; n4 = M_ * D_ / 4; break;
        case 1: src = k;  dst = g_xk16; n4 = M_ * D_ / 4; break;
        case 2: src = v;  dst = g_xv16; n4 = M_ * D_ / 4; break;
        case 3: src = wq; dst = g_wq16; n4 = D_ * D_ / 4; break;
        case 4: src = wk; dst = g_wk16; n4 = D_ * D_ / 4; break;
        case 5: src = wv; dst = g_wv16; n4 = D_ * D_ / 4; break;
        case 6: src = wo; dst = g_wo16; n4 = D_ * D_ / 4; break;
    }
    const int stride = gridDim.x * blockDim.x;
    const float4* s4 = reinterpret_cast<const float4*>(src);
    uint2* d2 = reinterpret_cast<uint2*>(dst);
    for (int i = blockIdx.x * blockDim.x + threadIdx.x; i < n4; i += stride) {
        float4 a = s4[i];
        uint2 u = {pack_h2(a.x, a.y), pack_h2(a.z, a.w)};
        d2[i] = u;
    }
}

// ---------------------------------------------------------------------------
// QKV GEMM 64x128 CTA tile, 128 threads (4 warps of m64n32), BK=32,
// 3-stage cp.async ring, one barrier per k-step, fp16 mma, fp32 accumulate.
// ---------------------------------------------------------------------------
#define GAP 40    // A pitch (halves)
#define GBP 136   // B pitch (halves, 128-wide tile)
#define GA_TILE (64 * GAP)    // 2560 halves
#define GB_TILE (32 * GBP)    // 4352 halves
#define GEMM_SMEM ((3 * GA_TILE + 3 * GB_TILE) * 2)   // 41472 B

__device__ __forceinline__ void gemm_stage(uint32_t adst, uint32_t bdst,
                                           const __half* __restrict__ A,
                                           const __half* __restrict__ W,
                                           int m0, int n0, int kb)
{
    const int tid = threadIdx.x;
#pragma unroll
    for (int i = 0; i < 2; i++) {
        int f   = tid + (i << 7);
        int row = f >> 2;
        int c8  = (f & 3) << 3;
        CP_ASYNC16(adst + (uint32_t)(row * GAP + c8) * 2u,
                   A + (size_t)(m0 + row) * D_ + kb + c8);
    }
#pragma unroll
    for (int i = 0; i < 4; i++) {
        int f   = tid + (i << 7);
        int row = f >> 4;
        int c8  = (f & 15) << 3;
        CP_ASYNC16(bdst + (uint32_t)(row * GBP + c8) * 2u,
                   W + (size_t)(kb + row) * D_ + n0 + c8);
    }
    asm volatile("cp.async.commit_group;");
}

__global__ __launch_bounds__(128)
void gemm_qkv(const float* __restrict__ bq, const float* __restrict__ bk,
              const float* __restrict__ bv)
{
    const int z = blockIdx.z;
    const __half* A = (z == 0) ? g_xq16 : (z == 1) ? g_xk16 : g_xv16;
    const __half* W = (z == 0) ? g_wq16 : (z == 1) ? g_wk16 : g_wv16;
    const float* bias = (z == 0) ? bq : (z == 1) ? bk : bv;
    __half* C = (z == 0) ? g_qh : (z == 1) ? g_kh : g_vh;
    const float osc = (z == 0) ? 0.125f * LOG2E : 1.0f;

    const uint32_t abase = smem_u32(dynsm);
    const uint32_t bbase = abase + 3u * GA_TILE * 2u;

    const int tid  = threadIdx.x;
    const int wc   = tid >> 5;
    const int lane = tid & 31;
    const int g    = lane >> 2;
    const int c    = lane & 3;
    const int m0   = blockIdx.x << 6;
    const int n0   = blockIdx.y << 7;

    const int lr8  = lane & 7;
    const int lhi  = (lane >> 3) & 1;
    const int lcol = lane >> 4;

    gemm_stage(abase, bbase, A, W, m0, n0, 0);
    gemm_stage(abase + GA_TILE * 2u, bbase + GB_TILE * 2u, A, W, m0, n0, 32);

    float acc[4][4][4];
#pragma unroll
    for (int mt = 0; mt < 4; mt++)
#pragma unroll
        for (int nt = 0; nt < 4; nt++)
#pragma unroll
            for (int r = 0; r < 4; r++) acc[mt][nt][r] = 0.f;

    const int niter = D_ / 32;
    for (int it = 0; it < niter; it++) {
        asm volatile("cp.async.wait_group 1;" ::: "memory");
        __syncthreads();

        const uint32_t as = abase + (uint32_t)(it % 3) * GA_TILE * 2u;
        const uint32_t bs = bbase + (uint32_t)(it % 3) * GB_TILE * 2u;

#pragma unroll
        for (int ks = 0; ks < 2; ks++) {
            uint32_t a[4][4];
#pragma unroll
            for (int mt = 0; mt < 4; mt++) {
                uint32_t addr = as + (uint32_t)(
                    (mt * 16 + lr8 + lhi * 8) * GAP + ks * 16 + lcol * 8) * 2u;
                LDSM_X4(a[mt][0], a[mt][1], a[mt][2], a[mt][3], addr);
            }
            uint32_t bfr[2][4];
#pragma unroll
            for (int np = 0; np < 2; np++) {
                uint32_t addr = bs + (uint32_t)(
                    (ks * 16 + lr8 + lhi * 8) * GBP
                    + wc * 32 + np * 16 + lcol * 8) * 2u;
                LDSM_X4_T(bfr[np][0], bfr[np][1], bfr[np][2], bfr[np][3], addr);
            }
#pragma unroll
            for (int mt = 0; mt < 4; mt++)
#pragma unroll
                for (int nt = 0; nt < 4; nt++)
                    mma_f16(acc[mt][nt], a[mt],
                            bfr[nt >> 1][(nt & 1) * 2],
                            bfr[nt >> 1][(nt & 1) * 2 + 1]);
        }

        if (it + 2 < niter)
            gemm_stage(abase + (uint32_t)((it + 2) % 3) * GA_TILE * 2u,
                       bbase + (uint32_t)((it + 2) % 3) * GB_TILE * 2u,
                       A, W, m0, n0, (it + 2) * 32);
        else
            asm volatile("cp.async.commit_group;");
    }

#pragma unroll
    for (int nt = 0; nt < 4; nt++) {
        int col = n0 + wc * 32 + nt * 8 + 2 * c;
        float bx = bias[col], by = bias[col + 1];
#pragma unroll
        for (int mt = 0; mt < 4; mt++) {
            int row = m0 + mt * 16 + g;
            *reinterpret_cast<uint32_t*>(C + (size_t)row * D_ + col) =
                pack_h2((acc[mt][nt][0] + bx) * osc, (acc[mt][nt][1] + by) * osc);
            *reinterpret_cast<uint32_t*>(C + (size_t)(row + 8) * D_ + col) =
                pack_h2((acc[mt][nt][2] + bx) * osc, (acc[mt][nt][3] + by) * osc);
        }
    }
}

// ---------------------------------------------------------------------------
// O-projection GEMM (round-12 variant): 64x64 CTA tile, BK=32, 1024 CTAs,
// fp32 output + bias.
// ---------------------------------------------------------------------------
#define GBP2 72                  // B pitch (halves, 64-wide tile)
#define GB2_TILE (32 * GBP2)     // 2304 halves
#define GEMM2_SMEM ((3 * GA_TILE + 3 * GB2_TILE) * 2)   // 29184 B

__device__ __forceinline__ void gemm2_stage(uint32_t adst, uint32_t bdst,
                                            int m0, int n0, int kb)
{
    const int tid = threadIdx.x;
#pragma unroll
    for (int i = 0; i < 2; i++) {
        int f   = tid + (i << 7);
        int row = f >> 2;
        int c8  = (f & 3) << 3;
        CP_ASYNC16(adst + (uint32_t)(row * GAP + c8) * 2u,
                   g_xth + (size_t)(m0 + row) * D_ + kb + c8);
    }
#pragma unroll
    for (int i = 0; i < 2; i++) {
        int f   = tid + (i << 7);
        int row = f >> 3;
        int c8  = (f & 7) << 3;
        CP_ASYNC16(bdst + (uint32_t)(row * GBP2 + c8) * 2u,
                   g_wo16 + (size_t)(kb + row) * D_ + n0 + c8);
    }
    asm volatile("cp.async.commit_group;");
}

__global__ __launch_bounds__(128)
void gemm_o(const float* __restrict__ bo, float* __restrict__ out)
{
    const uint32_t abase = smem_u32(dynsm);
    const uint32_t bbase = abase + 3u * GA_TILE * 2u;

    const int tid  = threadIdx.x;
    const int wc   = tid >> 5;
    const int lane = tid & 31;
    const int g    = lane >> 2;
    const int c    = lane & 3;
    const int m0   = blockIdx.x << 6;
    const int n0   = blockIdx.y << 6;

    const int lr8  = lane & 7;
    const int lhi  = (lane >> 3) & 1;
    const int lcol = lane >> 4;

    gemm2_stage(abase, bbase, m0, n0, 0);
    gemm2_stage(abase + GA_TILE * 2u, bbase + GB2_TILE * 2u, m0, n0, 32);

    float acc[4][2][4];
#pragma unroll
    for (int mt = 0; mt < 4; mt++)
#pragma unroll
        for (int nt = 0; nt < 2; nt++)
#pragma unroll
            for (int r = 0; r < 4; r++) acc[mt][nt][r] = 0.f;

    const int niter = D_ / 32;
    for (int it = 0; it < niter; it++) {
        asm volatile("cp.async.wait_group 1;" ::: "memory");
        __syncthreads();

        const uint32_t as = abase + (uint32_t)(it % 3) * GA_TILE * 2u;
        const uint32_t bs = bbase + (uint32_t)(it % 3) * GB2_TILE * 2u;

#pragma unroll
        for (int ks = 0; ks < 2; ks++) {
            uint32_t a[4][4];
#pragma unroll
            for (int mt = 0; mt < 4; mt++) {
                uint32_t addr = as + (uint32_t)(
                    (mt * 16 + lr8 + lhi * 8) * GAP + ks * 16 + lcol * 8) * 2u;
                LDSM_X4(a[mt][0], a[mt][1], a[mt][2], a[mt][3], addr);
            }
            uint32_t b0, b1, b2, b3;
            {
                uint32_t addr = bs + (uint32_t)(
                    (ks * 16 + lr8 + lhi * 8) * GBP2 + wc * 16 + lcol * 8) * 2u;
                LDSM_X4_T(b0, b1, b2, b3, addr);
            }
#pragma unroll
            for (int mt = 0; mt < 4; mt++) {
                mma_f16(acc[mt][0], a[mt], b0, b1);
                mma_f16(acc[mt][1], a[mt], b2, b3);
            }
        }

        if (it + 2 < niter)
            gemm2_stage(abase + (uint32_t)((it + 2) % 3) * GA_TILE * 2u,
                        bbase + (uint32_t)((it + 2) % 3) * GB2_TILE * 2u,
                        m0, n0, (it + 2) * 32);
        else
            asm volatile("cp.async.commit_group;");
    }

#pragma unroll
    for (int nt = 0; nt < 2; nt++) {
        int col = n0 + wc * 16 + nt * 8 + 2 * c;
        float bx = bo[col], by = bo[col + 1];
#pragma unroll
        for (int mt = 0; mt < 4; mt++) {
            int row = m0 + mt * 16 + g;
            *reinterpret_cast<float2*>(out + (size_t)row * D_ + col) =
                make_float2(acc[mt][nt][0] + bx, acc[mt][nt][1] + by);
            *reinterpret_cast<float2*>(out + (size_t)(row + 8) * D_ + col) =
                make_float2(acc[mt][nt][2] + bx, acc[mt][nt][3] + by);
        }
    }
}

// ---------------------------------------------------------------------------
// Flash attention: m16 warps, 3-stage ring, one barrier per tile.
// Mask loaded from fragment-ordered fp16 buffer (4 x LDG.128 per tile),
// fp32 softmax (convert-up, add, ex2.approx.f32), ones-mma row sum.
// ---------------------------------------------------------------------------
#define FPH 72                 // K/V smem pitch (halves)
#define FTILE_H (64 * FPH)     // 9216 B
#define FLASH_SMEM (6 * FTILE_H * 2)   // 55296 B
#define ONES_H2 0x3C003C00u

__device__ __forceinline__ void stage_kv(uint32_t kdst, uint32_t vdst,
                                         int b, int h, int k0)
{
    const int tid = threadIdx.x;
#pragma unroll
    for (int i = 0; i < 4; i++) {
        int f   = tid + (i << 7);
        int row = f >> 3;
        int s8  = (f & 7) << 3;
        size_t gidx = (((size_t)b * L_ + k0 + row) * H_ + h) * DK_ + s8;
        uint32_t off = (uint32_t)(row * FPH + s8) * 2u;
        CP_ASYNC16(kdst + off, g_kh + gidx);
        CP_ASYNC16(vdst + off, g_vh + gidx);
    }
    asm volatile("cp.async.commit_group;");
}

__global__ __launch_bounds__(128)
void flash_f16()
{
    const uint32_t base = smem_u32(dynsm);

    const int tid  = threadIdx.x;
    const int warp = tid >> 5;
    const int lane = tid & 31;
    const int g    = lane >> 2;
    const int c    = lane & 3;
    const int q0   = blockIdx.x << 6;
    const int h    = blockIdx.y;
    const int b    = blockIdx.z;
    const int qrow = q0 + warp * 16;

    uint32_t ks[3], vs[3];
#pragma unroll
    for (int i = 0; i < 3; i++) {
        ks[i] = base + (uint32_t)(i * FTILE_H) * 2u;
        vs[i] = base + (uint32_t)((3 + i) * FTILE_H) * 2u;
    }

    const int lr8 = lane & 7;
    const int lhi = (lane >> 3) & 1;
    const int lcol = lane >> 4;
    const uint32_t k_lane_off =
        (uint32_t)(lr8 * FPH + (lane >> 3) * 8) * 2u;
    const uint32_t v_lane_off =
        (uint32_t)((lr8 + lhi * 8) * FPH + lcol * 8) * 2u;

    stage_kv(ks[0], vs[0], b, h, 0);
    stage_kv(ks[1], vs[1], b, h, 64);

    // Q fragments (fp16, pre-scaled by 0.125*log2e)
    uint32_t qf[4][4];
    {
        const __half* qp = g_qh + (((size_t)b * L_ + qrow) * H_ + h) * DK_;
#pragma unroll
        for (int kb = 0; kb < 4; kb++) {
            int d0 = kb * 16 + 2 * c;
            qf[kb][0] = *reinterpret_cast<const uint32_t*>(
                qp + (size_t)(g)     * (H_ * DK_) + d0);
            qf[kb][1] = *reinterpret_cast<const uint32_t*>(
                qp + (size_t)(g + 8) * (H_ * DK_) + d0);
            qf[kb][2] = *reinterpret_cast<const uint32_t*>(
                qp + (size_t)(g)     * (H_ * DK_) + d0 + 8);
            qf[kb][3] = *reinterpret_cast<const uint32_t*>(
                qp + (size_t)(g + 8) * (H_ * DK_) + d0 + 8);
        }
    }

    float o[8][4];
    float lsum[4] = {0.f, 0.f, 0.f, 0.f};
#pragma unroll
    for (int nt = 0; nt < 8; nt++)
#pragma unroll
        for (int r = 0; r < 4; r++) o[nt][r] = 0.f;

    // Fragment-ordered mask base for this (qb, warp, lane): tile stride 4*32*16.
    const uint4* mbase = reinterpret_cast<const uint4*>(
        g_mp + ((((size_t)(q0 >> 6) * 32) * 4 + warp) * 32 + lane) * 16);
    const size_t mtile_stride = 4 * 32 * 16 / 4;   // uint4 units per tile step

    for (int t = 0; t < 32; t++) {
        asm volatile("cp.async.wait_group 1;" ::: "memory");
        __syncthreads();

        const uint32_t kb_sm = ks[t % 3];
        const uint32_t vb_sm = vs[t % 3];

        // Mask tile: 4 x LDG.128, fully coalesced (fragment order).
        uint4 m4[4];
        {
            const uint4* mt = mbase + (size_t)t * mtile_stride;
            m4[0] = mt[0]; m4[1] = mt[1]; m4[2] = mt[2]; m4[3] = mt[3];
        }
        const uint32_t* mh = reinterpret_cast<const uint32_t*>(m4);

        // S' = (Q*log2e/8) K^T
        float s[8][4];
#pragma unroll
        for (int nt = 0; nt < 8; nt++)
#pragma unroll
            for (int r = 0; r < 4; r++) s[nt][r] = 0.f;

#pragma unroll
        for (int nt = 0; nt < 8; nt++) {
#pragma unroll
            for (int kb2 = 0; kb2 < 2; kb2++) {
                uint32_t r0, r1, r2, r3;
                uint32_t addr = kb_sm
                    + (uint32_t)(nt * 8 * FPH + kb2 * 32) * 2u + k_lane_off;
                LDSM_X4(r0, r1, r2, r3, addr);
                mma_f16(s[nt], qf[2 * kb2],     r0, r1);
                mma_f16(s[nt], qf[2 * kb2 + 1], r2, r3);
            }
        }

        // fp32 softmax: convert fp16 mask up, add, ex2.f32, pack P
        uint32_t ph[8][2];
#pragma unroll
        for (int nt = 0; nt < 8; nt++) {
            float2 m0f = __half22float2(
                *reinterpret_cast<const __half2*>(&mh[2 * nt]));
            float2 m1f = __half22float2(
                *reinterpret_cast<const __half2*>(&mh[2 * nt + 1]));
            float p0 = ex2f(s[nt][0] + m0f.x);
            float p1 = ex2f(s[nt][1] + m0f.y);
            float p2 = ex2f(s[nt][2] + m1f.x);
            float p3 = ex2f(s[nt][3] + m1f.y);
            ph[nt][0] = pack_h2(p0, p1);
            ph[nt][1] = pack_h2(p2, p3);
        }

        // O += P V ; l += P @ ones
#pragma unroll
        for (int j = 0; j < 4; j++) {
            uint32_t a[4] = {ph[2 * j][0], ph[2 * j][1],
                             ph[2 * j + 1][0], ph[2 * j + 1][1]};
            mma_f16(lsum, a, ONES_H2, ONES_H2);
#pragma unroll
            for (int np = 0; np < 4; np++) {
                uint32_t r0, r1, r2, r3;
                uint32_t addr = vb_sm
                    + (uint32_t)(j * 16 * FPH + np * 16) * 2u + v_lane_off;
                LDSM_X4_T(r0, r1, r2, r3, addr);
                mma_f16(o[2 * np],     a, r0, r1);
                mma_f16(o[2 * np + 1], a, r2, r3);
            }
        }

        if (t + 2 < 32)
            stage_kv(ks[(t + 2) % 3], vs[(t + 2) % 3], b, h, (t + 2) << 6);
        else
            asm volatile("cp.async.commit_group;");
    }

    float inv0 = 1.0f / lsum[0], inv1 = 1.0f / lsum[2];

    // Epilogue: write g_xth (fp16) in [H, Lq, B, Dv] flat order
#pragma unroll
    for (int nt = 0; nt < 8; nt++) {
        int dv = nt * 8 + 2 * c;
        size_t base0 = (((size_t)h * L_ + qrow + g) * B_ + b) * DK_ + dv;
        size_t base1 = (((size_t)h * L_ + qrow + g + 8) * B_ + b) * DK_ + dv;
        *reinterpret_cast<uint32_t*>(g_xth + base0) =
            pack_h2(o[nt][0] * inv0, o[nt][1] * inv0);
        *reinterpret_cast<uint32_t*>(g_xth + base1) =
            pack_h2(o[nt][2] * inv1, o[nt][3] * inv1);
    }
}

// ---------------------------------------------------------------------------
extern "C" void kernel_launch(void* const* d_in, const int* in_sizes, int n_in,
                              void* d_out, int out_size)
{
    const float* query = (const float*)d_in[0];
    const float* key   = (const float*)d_in[1];
    const float* value = (const float*)d_in[2];
    const float* mask  = (const float*)d_in[3];
    const float* Wq    = (const float*)d_in[4];
    const float* bq    = (const float*)d_in[5];
    const float* Wk    = (const float*)d_in[6];
    const float* bk    = (const float*)d_in[7];
    const float* Wv    = (const float*)d_in[8];
    const float* bv    = (const float*)d_in[9];
    const float* Wo    = (const float*)d_in[10];
    const float* bo    = (const float*)d_in[11];
    float* out = (float*)d_out;

    cudaFuncSetAttribute(gemm_qkv,
                         cudaFuncAttributeMaxDynamicSharedMemorySize, GEMM_SMEM);
    cudaFuncSetAttribute(gemm_o,
                         cudaFuncAttributeMaxDynamicSharedMemorySize, GEMM2_SMEM);
    cudaFuncSetAttribute(flash_f16,
                         cudaFuncAttributeMaxDynamicSharedMemorySize, FLASH_SMEM);

    prep_f16<<<dim3(512, 8), 256>>>(query, key, value, Wq, Wk, Wv, Wo, mask);

    gemm_qkv<<<dim3(M_ / 64, D_ / 128, 3), 128, GEMM_SMEM>>>(bq, bk, bv);

    flash_f16<<<dim3(L_ / 64, H_, B_), 128, FLASH_SMEM>>>();

    gemm_o<<<dim3(M_ / 64, D_ / 64), 128, GEMM2_SMEM>>>(bo, out);
}